// round 6
// baseline (speedup 1.0000x reference)
#include <cuda_runtime.h>
#include <cuda_bf16.h>
#include <cstdint>

#define N_NODES 8192
#define F_DIM   256
#define H_DIM   64
#define NS      80      // padded B rows: 64 h-feats + 1 ones (deg) + 15 zero
#define KSPLIT  8
#define MT      128
#define KC      64

// ---------------- scratch (static device globals; no allocation) ----------------
__device__ __align__(16) float          d_WtT[F_DIM * H_DIM];       // [256][64]
__device__ __align__(16) float          d_WpT[H_DIM * F_DIM];       // [64][256]
__device__ __align__(16) __nv_bfloat16  d_hT[NS * N_NODES];         // [80][8192]
__device__ __align__(16) float          d_part[(size_t)KSPLIT * N_NODES * NS]; // ~21MB
__device__ __align__(16) float          d_hsum[H_DIM];

// ---------------- K0: transpose weights, fill padded hT rows ----------------
__global__ void k0_prep(const float* __restrict__ Wt, const float* __restrict__ Wp) {
    int i = blockIdx.x * blockDim.x + threadIdx.x;
    if (i < 16384) {
        int f = i >> 6, t = i & 63;
        d_WtT[i] = Wt[t * 256 + f];                 // WtT[f][t] = Wt[t][f]
    } else if (i < 32768) {
        int j = i - 16384;
        int t = j >> 8, f = j & 255;
        d_WpT[j] = Wp[f * 64 + t];                  // WpT[t][f] = Wp[f][t]
    } else if (i < 32768 + 16 * 8192) {
        int j = i - 32768;
        int r = j >> 13, c = j & 8191;              // rows 64..79
        d_hT[(64 + r) * 8192 + c] = (r == 0) ? __float2bfloat16(1.0f)
                                             : __float2bfloat16(0.0f);
    }
}

// ---------------- K1: h = x@Wt^T + bt, write transposed bf16 hT[t][node] ----------------
__global__ __launch_bounds__(256) void k1_feat(const float* __restrict__ x,
                                               const float* __restrict__ bt) {
    __shared__ float xs[64 * 65];   // [node][f] padded
    __shared__ float ws[64 * 64];   // [f][t]
    int tid = threadIdx.x;
    int i0  = blockIdx.x * 64;
    int t   = tid & 63, grp = tid >> 6;     // grp 0..3, 16 nodes each
    float acc[16];
#pragma unroll
    for (int j = 0; j < 16; ++j) acc[j] = 0.f;

    for (int c = 0; c < 4; ++c) {           // f-chunks of 64
        __syncthreads();
#pragma unroll
        for (int it = 0; it < 16; ++it) {
            int idx = it * 256 + tid;
            int n = idx >> 6, f = idx & 63;
            xs[n * 65 + f] = x[(size_t)(i0 + n) * 256 + c * 64 + f];
            ws[idx]        = d_WtT[c * 4096 + idx];
        }
        __syncthreads();
#pragma unroll 8
        for (int f = 0; f < 64; ++f) {
            float wv = ws[f * 64 + t];
#pragma unroll
            for (int j = 0; j < 16; ++j)
                acc[j] += xs[(grp * 16 + j) * 65 + f] * wv;
        }
    }
    float bv = bt[t];
#pragma unroll
    for (int j = 0; j < 16; ++j) {
        int node = i0 + grp * 16 + j;
        d_hT[t * 8192 + node] = __float2bfloat16(acc[j] + bv);
    }
}

// ---------------- K1b: column sums of h (deg==0 fallback) ----------------
__global__ void k1b_hsum() {
    int t = blockIdx.x, tid = threadIdx.x;
    float s = 0.f;
    for (int i = tid; i < 8192; i += 256)
        s += __bfloat162float(d_hT[t * 8192 + i]);
#pragma unroll
    for (int off = 16; off; off >>= 1) s += __shfl_xor_sync(0xffffffffu, s, off);
    __shared__ float red[8];
    if ((tid & 31) == 0) red[tid >> 5] = s;
    __syncthreads();
    if (tid == 0) {
        float tot = 0.f;
        for (int w = 0; w < 8; ++w) tot += red[w];
        d_hsum[t] = tot;
    }
}

// ---------------- K2: SpMM  part[ks] = adj_tile @ [h | 1] via bf16 mma.sync ----------------
__global__ __launch_bounds__(256) void k2_spmm(const int* __restrict__ adj) {
    __shared__ __align__(16) unsigned char As[MT * 128];  // 128 rows x 64 bf16 (128B), XOR-swizzled
    __shared__ __align__(16) unsigned char Bs[NS * 128];  // 80 rows x 64 bf16
    int tid  = threadIdx.x;
    int lane = tid & 31, warp = tid >> 5;
    int mw   = warp & 3, nw = warp >> 2;                  // 4 M-groups x 2 N-groups
    int i0    = blockIdx.x * MT;
    int ks    = blockIdx.y;
    int kbase = ks * (N_NODES / KSPLIT);

    float c[2][5][4];
#pragma unroll
    for (int a = 0; a < 2; ++a)
#pragma unroll
        for (int b = 0; b < 5; ++b)
#pragma unroll
            for (int q = 0; q < 4; ++q) c[a][b][q] = 0.f;

    for (int ch = 0; ch < (N_NODES / KSPLIT) / KC; ++ch) {
        int kc0 = kbase + ch * KC;
        __syncthreads();
        // A: stream adj int32, convert {0,1} -> bf16 {0, 1.0} with IMAD packing
#pragma unroll
        for (int it = 0; it < 8; ++it) {
            int idx = it * 256 + tid;                 // 0..2047
            int r = idx >> 4, u4 = idx & 15;
            const int4 av = *(const int4*)(adj + (size_t)(i0 + r) * N_NODES + kc0 + u4 * 4);
            unsigned lo = (unsigned)av.x * 0x3F80u + (unsigned)av.y * 0x3F800000u;
            unsigned hi = (unsigned)av.z * 0x3F80u + (unsigned)av.w * 0x3F800000u;
            int u = u4 >> 1, half = u4 & 1;
            int su = u ^ (r & 7);
            *(uint2*)(As + r * 128 + su * 16 + half * 8) = make_uint2(lo, hi);
        }
        // B: stage hT chunk (K-major rows), same swizzle
#pragma unroll
        for (int it = 0; it < 3; ++it) {
            int idx = it * 256 + tid;
            if (idx < NS * 8) {
                int r = idx >> 3, u = idx & 7;
                uint4 v = *(const uint4*)((const unsigned char*)d_hT +
                                          (size_t)r * (N_NODES * 2) + (size_t)kc0 * 2 + u * 16);
                *(uint4*)(Bs + r * 128 + (u ^ (r & 7)) * 16) = v;
            }
        }
        __syncthreads();
#pragma unroll
        for (int kk = 0; kk < 4; ++kk) {              // 4 x k16 steps
            unsigned afr[2][4];
#pragma unroll
            for (int mf = 0; mf < 2; ++mf) {
                int sub = lane >> 3;
                int row = mw * 32 + mf * 16 + ((sub & 1) << 3) + (lane & 7);
                int u   = 2 * kk + (sub >> 1);
                unsigned ad = (unsigned)__cvta_generic_to_shared(
                    As + row * 128 + (u ^ (row & 7)) * 16);
                asm volatile("ldmatrix.sync.aligned.m8n8.x4.shared.b16 {%0,%1,%2,%3}, [%4];"
                             : "=r"(afr[mf][0]), "=r"(afr[mf][1]),
                               "=r"(afr[mf][2]), "=r"(afr[mf][3]) : "r"(ad));
            }
            unsigned bfr[5][2];
#pragma unroll
            for (int nf = 0; nf < 5; ++nf) {
                int row = nw * 40 + nf * 8 + (lane & 7);
                int u   = 2 * kk + ((lane >> 3) & 1);
                unsigned ad = (unsigned)__cvta_generic_to_shared(
                    Bs + row * 128 + (u ^ (row & 7)) * 16);
                asm volatile("ldmatrix.sync.aligned.m8n8.x2.shared.b16 {%0,%1}, [%2];"
                             : "=r"(bfr[nf][0]), "=r"(bfr[nf][1]) : "r"(ad));
            }
#pragma unroll
            for (int mf = 0; mf < 2; ++mf)
#pragma unroll
                for (int nf = 0; nf < 5; ++nf)
                    asm volatile(
                        "mma.sync.aligned.m16n8k16.row.col.f32.bf16.bf16.f32 "
                        "{%0,%1,%2,%3}, {%4,%5,%6,%7}, {%8,%9}, {%0,%1,%2,%3};"
                        : "+f"(c[mf][nf][0]), "+f"(c[mf][nf][1]),
                          "+f"(c[mf][nf][2]), "+f"(c[mf][nf][3])
                        : "r"(afr[mf][0]), "r"(afr[mf][1]), "r"(afr[mf][2]), "r"(afr[mf][3]),
                          "r"(bfr[nf][0]), "r"(bfr[nf][1]));
        }
    }
    // store partial tile to split buffer (deterministic, no atomics)
    int gr = lane >> 2, gc = (lane & 3) * 2;
    size_t base = (size_t)ks * N_NODES * NS;
#pragma unroll
    for (int mf = 0; mf < 2; ++mf)
#pragma unroll
        for (int nf = 0; nf < 5; ++nf) {
            int m0 = i0 + mw * 32 + mf * 16 + gr;
            int n0 = nw * 40 + nf * 8 + gc;
            *(float2*)&d_part[base + (size_t)m0 * NS + n0]       = make_float2(c[mf][nf][0], c[mf][nf][1]);
            *(float2*)&d_part[base + (size_t)(m0 + 8) * NS + n0] = make_float2(c[mf][nf][2], c[mf][nf][3]);
        }
}

// ---------------- K3: reduce splits, /deg, @Wp^T + bp, residual, LayerNorm ----------------
__global__ __launch_bounds__(256) void k3_epilogue(const float* __restrict__ x,
                                                   const float* __restrict__ bp,
                                                   const float* __restrict__ gamma,
                                                   const float* __restrict__ beta,
                                                   float* __restrict__ out) {
    __shared__ float nb[8][80];
    __shared__ float degs[8];
    __shared__ float red[8][16];
    __shared__ float stats[16];
    int tid = threadIdx.x;
    int i0  = blockIdx.x * 8;          // 8 nodes per block

#pragma unroll
    for (int it = 0; it < 3; ++it) {
        int idx = it * 256 + tid;
        if (idx < 640) {
            int nd = idx / 80, t = idx - nd * 80;
            size_t off = (size_t)(i0 + nd) * NS + t;
            float s = 0.f;
#pragma unroll
            for (int ks = 0; ks < 8; ++ks)
                s += d_part[(size_t)ks * N_NODES * NS + off];
            nb[nd][t] = s;
        }
    }
    __syncthreads();
    if (tid < 8) degs[tid] = nb[tid][64];     // ones-column = degree
    __syncthreads();
#pragma unroll
    for (int it = 0; it < 2; ++it) {
        int idx = it * 256 + tid;             // 512 = 8 nodes x 64 feats
        int nd = idx >> 6, t = idx & 63;
        float d = degs[nd];
        nb[nd][t] = (d > 0.5f) ? nb[nd][t] * (1.0f / d)
                               : d_hsum[t] * (1.0f / 8192.0f);  // uniform-softmax fallback
    }
    __syncthreads();

    int f = tid;
    float acc[8];
#pragma unroll
    for (int nd = 0; nd < 8; ++nd) acc[nd] = 0.f;
#pragma unroll 8
    for (int t = 0; t < 64; ++t) {
        float wv = d_WpT[t * 256 + f];
#pragma unroll
        for (int nd = 0; nd < 8; ++nd) acc[nd] += nb[nd][t] * wv;
    }
    float bpf = bp[f];
    float y[8], s1[8], s2[8];
#pragma unroll
    for (int nd = 0; nd < 8; ++nd) {
        y[nd]  = x[(size_t)(i0 + nd) * 256 + f] + acc[nd] + bpf;
        s1[nd] = y[nd];
        s2[nd] = y[nd] * y[nd];
    }
#pragma unroll
    for (int off = 16; off; off >>= 1)
#pragma unroll
        for (int nd = 0; nd < 8; ++nd) {
            s1[nd] += __shfl_xor_sync(0xffffffffu, s1[nd], off);
            s2[nd] += __shfl_xor_sync(0xffffffffu, s2[nd], off);
        }
    int lane = tid & 31, warp = tid >> 5;
    if (lane == 0) {
#pragma unroll
        for (int nd = 0; nd < 8; ++nd) {
            red[warp][nd * 2]     = s1[nd];
            red[warp][nd * 2 + 1] = s2[nd];
        }
    }
    __syncthreads();
    if (tid < 16) {
        float tot = 0.f;
#pragma unroll
        for (int w = 0; w < 8; ++w) tot += red[w][tid];
        stats[tid] = tot;
    }
    __syncthreads();
    float g = gamma[f], bb = beta[f];
#pragma unroll
    for (int nd = 0; nd < 8; ++nd) {
        float mu  = stats[nd * 2] * (1.0f / 256.0f);
        float var = stats[nd * 2 + 1] * (1.0f / 256.0f) - mu * mu;
        out[(size_t)(i0 + nd) * 256 + f] = g * (y[nd] - mu) * rsqrtf(var + 1e-5f) + bb;
    }
}

// ---------------- launch ----------------
extern "C" void kernel_launch(void* const* d_in, const int* in_sizes, int n_in,
                              void* d_out, int out_size) {
    const float* x     = (const float*)d_in[0];
    const int*   adj   = (const int*)  d_in[1];
    const float* Wt    = (const float*)d_in[2];
    const float* bt    = (const float*)d_in[3];
    // d_in[4] = Wa, d_in[5] = ba : provably unused (softmax is degenerate per row)
    const float* Wp    = (const float*)d_in[6];
    const float* bp    = (const float*)d_in[7];
    const float* gamma = (const float*)d_in[8];
    const float* beta  = (const float*)d_in[9];
    float* out = (float*)d_out;

    k0_prep<<<640, 256>>>(Wt, Wp);
    k1_feat<<<128, 256>>>(x, bt);
    k1b_hsum<<<64, 256>>>();
    k2_spmm<<<dim3(64, 8), 256>>>(adj);
    k3_epilogue<<<1024, 256>>>(x, bp, gamma, beta, out);
}

// round 7
// speedup vs baseline: 1.5123x; 1.5123x over previous
#include <cuda_runtime.h>
#include <cuda_bf16.h>
#include <cstdint>

#define N_NODES 8192
#define F_DIM   256
#define H_DIM   64
#define NS      80      // padded B rows: 64 h-feats + 1 ones (deg) + 15 zero
#define KSPLIT  4
#define MT      64      // M rows per CTA (4 warps x 16)
#define KC      64      // K chunk

// ---------------- scratch (static device globals; no allocation) ----------------
__device__ __align__(16) float          d_WtT[F_DIM * H_DIM];       // [256][64]
__device__ __align__(16) float          d_WpT[H_DIM * F_DIM];       // [64][256]
__device__ __align__(16) __nv_bfloat16  d_hT[NS * N_NODES];         // [80][8192]
__device__ __align__(16) float          d_part[(size_t)KSPLIT * N_NODES * NS]; // ~10.5MB
__device__ __align__(16) float          d_hsum[H_DIM];

// ---------------- K0: transpose weights, fill padded hT rows ----------------
__global__ void k0_prep(const float* __restrict__ Wt, const float* __restrict__ Wp) {
    int i = blockIdx.x * blockDim.x + threadIdx.x;
    if (i < 16384) {
        int f = i >> 6, t = i & 63;
        d_WtT[i] = Wt[t * 256 + f];
    } else if (i < 32768) {
        int j = i - 16384;
        int t = j >> 8, f = j & 255;
        d_WpT[j] = Wp[f * 64 + t];
    } else if (i < 32768 + 16 * 8192) {
        int j = i - 32768;
        int r = j >> 13, c = j & 8191;              // rows 64..79
        d_hT[(64 + r) * 8192 + c] = (r == 0) ? __float2bfloat16(1.0f)
                                             : __float2bfloat16(0.0f);
    }
}

// ---------------- K1: h = x@Wt^T + bt, write transposed bf16 hT[t][node] ----------------
__global__ __launch_bounds__(256) void k1_feat(const float* __restrict__ x,
                                               const float* __restrict__ bt) {
    __shared__ float xs[64 * 65];
    __shared__ float ws[64 * 64];
    int tid = threadIdx.x;
    int i0  = blockIdx.x * 64;
    int t   = tid & 63, grp = tid >> 6;
    float acc[16];
#pragma unroll
    for (int j = 0; j < 16; ++j) acc[j] = 0.f;

    for (int c = 0; c < 4; ++c) {
        __syncthreads();
#pragma unroll
        for (int it = 0; it < 16; ++it) {
            int idx = it * 256 + tid;
            int n = idx >> 6, f = idx & 63;
            xs[n * 65 + f] = x[(size_t)(i0 + n) * 256 + c * 64 + f];
            ws[idx]        = d_WtT[c * 4096 + idx];
        }
        __syncthreads();
#pragma unroll 8
        for (int f = 0; f < 64; ++f) {
            float wv = ws[f * 64 + t];
#pragma unroll
            for (int j = 0; j < 16; ++j)
                acc[j] += xs[(grp * 16 + j) * 65 + f] * wv;
        }
    }
    float bv = bt[t];
#pragma unroll
    for (int j = 0; j < 16; ++j) {
        int node = i0 + grp * 16 + j;
        d_hT[t * 8192 + node] = __float2bfloat16(acc[j] + bv);
    }
}

// ---------------- K1b: column sums of h (deg==0 fallback) ----------------
__global__ void k1b_hsum() {
    int t = blockIdx.x, tid = threadIdx.x;
    float s = 0.f;
    for (int i = tid; i < 8192; i += 256)
        s += __bfloat162float(d_hT[t * 8192 + i]);
#pragma unroll
    for (int off = 16; off; off >>= 1) s += __shfl_xor_sync(0xffffffffu, s, off);
    __shared__ float red[8];
    if ((tid & 31) == 0) red[tid >> 5] = s;
    __syncthreads();
    if (tid == 0) {
        float tot = 0.f;
        for (int w = 0; w < 8; ++w) tot += red[w];
        d_hsum[t] = tot;
    }
}

// ---------------- K2: SpMM, adj streamed straight global->register->mma ----------------
__device__ __forceinline__ void cp16(unsigned dst, const void* src) {
    asm volatile("cp.async.cg.shared.global [%0], [%1], 16;\n" :: "r"(dst), "l"(src));
}
__device__ __forceinline__ unsigned cvt01(int lo, int hi) {
    // {0,1} ints -> packed bf16x2 {0, 1.0f}
    return (unsigned)lo * 0x3F80u + (unsigned)hi * 0x3F800000u;
}

__global__ __launch_bounds__(128, 4) void k2_spmm(const int* __restrict__ adj) {
    __shared__ __align__(16) unsigned char Bs[2][NS * 128];
    int tid  = threadIdx.x;
    int lane = tid & 31, mw = tid >> 5;
    int i0    = blockIdx.x * MT;
    int ks    = blockIdx.y;
    int kbase = ks * (N_NODES / KSPLIT);
    const int NCH = (N_NODES / KSPLIT) / KC;   // 32

    float c[10][4];
#pragma unroll
    for (int nf = 0; nf < 10; ++nf)
#pragma unroll
        for (int q = 0; q < 4; ++q) c[nf][q] = 0.f;

    // B prefetch (stage, chunk base): 640 16B units, 5 per thread
#define PREFETCH_B(stage, kc0)                                                        \
    {                                                                                 \
        _Pragma("unroll")                                                             \
        for (int i = 0; i < 5; ++i) {                                                 \
            int idx = tid + i * 128;                                                  \
            int r = idx >> 3, u = idx & 7;                                            \
            const unsigned char* src = (const unsigned char*)d_hT +                   \
                (size_t)r * (N_NODES * 2) + (size_t)(kc0) * 2 + u * 16;               \
            unsigned dst = (unsigned)__cvta_generic_to_shared(                        \
                &Bs[stage][r * 128 + ((u ^ (r & 7)) * 16)]);                          \
            cp16(dst, src);                                                           \
        }                                                                             \
        asm volatile("cp.async.commit_group;\n");                                     \
    }

    PREFETCH_B(0, kbase);

    int g = lane >> 2, tg = lane & 3;
    int rowA = i0 + mw * 16 + g;
    const int* aptr0 = adj + (size_t)rowA * N_NODES + kbase + tg * 2;
    const int* aptr1 = aptr0 + (size_t)8 * N_NODES;

    for (int ch = 0; ch < NCH; ++ch) {
        int cur  = ch & 1;
        int coff = ch * KC;
        // A: 16 independent LDG.64 straight from global (sector-perfect)
        int2 araw[4][2][2];   // [kk][rowsel][khalf]
#pragma unroll
        for (int kk = 0; kk < 4; ++kk)
#pragma unroll
            for (int h = 0; h < 2; ++h) {
                araw[kk][0][h] = *(const int2*)(aptr0 + coff + kk * 16 + h * 8);
                araw[kk][1][h] = *(const int2*)(aptr1 + coff + kk * 16 + h * 8);
            }
        if (ch + 1 < NCH) {
            PREFETCH_B(cur ^ 1, kbase + (ch + 1) * KC);
            asm volatile("cp.async.wait_group 1;\n");
        } else {
            asm volatile("cp.async.wait_group 0;\n");
        }
        __syncthreads();

#pragma unroll
        for (int kk = 0; kk < 4; ++kk) {
            unsigned a0 = cvt01(araw[kk][0][0].x, araw[kk][0][0].y);
            unsigned a1 = cvt01(araw[kk][1][0].x, araw[kk][1][0].y);
            unsigned a2 = cvt01(araw[kk][0][1].x, araw[kk][0][1].y);
            unsigned a3 = cvt01(araw[kk][1][1].x, araw[kk][1][1].y);
            unsigned b[10][2];
#pragma unroll
            for (int p = 0; p < 5; ++p) {
                int row = p * 16 + (lane & 7) + (((lane >> 4) & 1) << 3);
                int u   = 2 * kk + ((lane >> 3) & 1);
                unsigned ad = (unsigned)__cvta_generic_to_shared(
                    &Bs[cur][row * 128 + ((u ^ (row & 7)) * 16)]);
                asm volatile("ldmatrix.sync.aligned.m8n8.x4.shared.b16 {%0,%1,%2,%3}, [%4];"
                             : "=r"(b[2 * p][0]), "=r"(b[2 * p][1]),
                               "=r"(b[2 * p + 1][0]), "=r"(b[2 * p + 1][1]) : "r"(ad));
            }
#pragma unroll
            for (int nf = 0; nf < 10; ++nf)
                asm volatile(
                    "mma.sync.aligned.m16n8k16.row.col.f32.bf16.bf16.f32 "
                    "{%0,%1,%2,%3}, {%4,%5,%6,%7}, {%8,%9}, {%0,%1,%2,%3};"
                    : "+f"(c[nf][0]), "+f"(c[nf][1]), "+f"(c[nf][2]), "+f"(c[nf][3])
                    : "r"(a0), "r"(a1), "r"(a2), "r"(a3),
                      "r"(b[nf][0]), "r"(b[nf][1]));
        }
        __syncthreads();   // protect Bs[cur] before next iter's prefetch overwrites it
    }

    // store partial tile (deterministic split buffer, no atomics)
    size_t base = (size_t)ks * N_NODES * NS;
    int gc = tg * 2;
#pragma unroll
    for (int nf = 0; nf < 10; ++nf) {
        int n0 = nf * 8 + gc;
        *(float2*)&d_part[base + (size_t)rowA * NS + n0]       = make_float2(c[nf][0], c[nf][1]);
        *(float2*)&d_part[base + (size_t)(rowA + 8) * NS + n0] = make_float2(c[nf][2], c[nf][3]);
    }
#undef PREFETCH_B
}

// ---------------- K3: reduce splits, /deg, @Wp^T + bp, residual, LayerNorm ----------------
__global__ __launch_bounds__(256) void k3_epilogue(const float* __restrict__ x,
                                                   const float* __restrict__ bp,
                                                   const float* __restrict__ gamma,
                                                   const float* __restrict__ beta,
                                                   float* __restrict__ out) {
    __shared__ float nb[8][80];
    __shared__ float degs[8];
    __shared__ float red[8][16];
    __shared__ float stats[16];
    int tid = threadIdx.x;
    int i0  = blockIdx.x * 8;

#pragma unroll
    for (int it = 0; it < 3; ++it) {
        int idx = it * 256 + tid;
        if (idx < 640) {
            int nd = idx / 80, t = idx - nd * 80;
            size_t off = (size_t)(i0 + nd) * NS + t;
            float s = 0.f;
#pragma unroll
            for (int ks = 0; ks < KSPLIT; ++ks)
                s += d_part[(size_t)ks * N_NODES * NS + off];
            nb[nd][t] = s;
        }
    }
    __syncthreads();
    if (tid < 8) degs[tid] = nb[tid][64];     // ones-column = degree
    __syncthreads();
#pragma unroll
    for (int it = 0; it < 2; ++it) {
        int idx = it * 256 + tid;
        int nd = idx >> 6, t = idx & 63;
        float d = degs[nd];
        nb[nd][t] = (d > 0.5f) ? nb[nd][t] * (1.0f / d)
                               : d_hsum[t] * (1.0f / 8192.0f);  // uniform fallback
    }
    __syncthreads();

    int f = tid;
    float acc[8];
#pragma unroll
    for (int nd = 0; nd < 8; ++nd) acc[nd] = 0.f;
#pragma unroll 8
    for (int t = 0; t < 64; ++t) {
        float wv = d_WpT[t * 256 + f];
#pragma unroll
        for (int nd = 0; nd < 8; ++nd) acc[nd] += nb[nd][t] * wv;
    }
    float bpf = bp[f];
    float y[8], s1[8], s2[8];
#pragma unroll
    for (int nd = 0; nd < 8; ++nd) {
        y[nd]  = x[(size_t)(i0 + nd) * 256 + f] + acc[nd] + bpf;
        s1[nd] = y[nd];
        s2[nd] = y[nd] * y[nd];
    }
#pragma unroll
    for (int off = 16; off; off >>= 1)
#pragma unroll
        for (int nd = 0; nd < 8; ++nd) {
            s1[nd] += __shfl_xor_sync(0xffffffffu, s1[nd], off);
            s2[nd] += __shfl_xor_sync(0xffffffffu, s2[nd], off);
        }
    int lane = tid & 31, warp = tid >> 5;
    if (lane == 0) {
#pragma unroll
        for (int nd = 0; nd < 8; ++nd) {
            red[warp][nd * 2]     = s1[nd];
            red[warp][nd * 2 + 1] = s2[nd];
        }
    }
    __syncthreads();
    if (tid < 16) {
        float tot = 0.f;
#pragma unroll
        for (int w = 0; w < 8; ++w) tot += red[w][tid];
        stats[tid] = tot;
    }
    __syncthreads();
    float g = gamma[f], bb = beta[f];
#pragma unroll
    for (int nd = 0; nd < 8; ++nd) {
        float mu  = stats[nd * 2] * (1.0f / 256.0f);
        float var = stats[nd * 2 + 1] * (1.0f / 256.0f) - mu * mu;
        out[(size_t)(i0 + nd) * 256 + f] = g * (y[nd] - mu) * rsqrtf(var + 1e-5f) + bb;
    }
}

// ---------------- launch ----------------
extern "C" void kernel_launch(void* const* d_in, const int* in_sizes, int n_in,
                              void* d_out, int out_size) {
    const float* x     = (const float*)d_in[0];
    const int*   adj   = (const int*)  d_in[1];
    const float* Wt    = (const float*)d_in[2];
    const float* bt    = (const float*)d_in[3];
    // d_in[4]=Wa, d_in[5]=ba provably unused (row-constant score -> degenerate softmax)
    const float* Wp    = (const float*)d_in[6];
    const float* bp    = (const float*)d_in[7];
    const float* gamma = (const float*)d_in[8];
    const float* beta  = (const float*)d_in[9];
    float* out = (float*)d_out;

    k0_prep<<<640, 256>>>(Wt, Wp);
    k1_feat<<<128, 256>>>(x, bt);
    k1b_hsum<<<64, 256>>>();
    k2_spmm<<<dim3(N_NODES / MT, KSPLIT), 128>>>(adj);
    k3_epilogue<<<1024, 256>>>(x, bp, gamma, beta, out);
}